// round 10
// baseline (speedup 1.0000x reference)
#include <cuda_runtime.h>
#include <cstdint>

#define BATCH 4
#define C_IN 32
#define C_OUT 32
#define NNODE 163842
#define K7 7

#define TM 128                           // nodes per CTA
#define THREADS 128                      // 4 warps
#define NT2 ((NNODE + TM - 1) / TM)      // 1281
#define PITCH 36                         // A row pitch in floats (144B, 16B-mult)

// ---- global scratch ----
__device__ float g_xt[(size_t)BATCH * NNODE * C_IN];   // x transposed [B,N,32]
// W fragment images, hi/lo interleaved per 16B: [j][ks][nb][lane][bh0 bh1 bl0 bl1]
__device__ float g_wimg[K7 * 16 * 32 * 4];             // 14336 floats = 56KB
__constant__ float cB[C_OUT];

// ---- smem layout (bytes) ----
#define SM_A     0                        // 2 bufs x TM x 144 = 36864
#define SM_W     36864                    // 57344
#define SM_MBAR  94208                    // 2 x 8
#define SM_TOTAL 94224

// ---------------------------------------------------------------------------
// helpers
// ---------------------------------------------------------------------------
__device__ __forceinline__ uint32_t s2u(const void* p) {
    uint32_t a;
    asm("{ .reg .u64 t; cvta.to.shared.u64 t, %1; cvt.u32.u64 %0, t; }"
        : "=r"(a) : "l"(p));
    return a;
}
#define MBAR_INIT(a, c) asm volatile("mbarrier.init.shared.b64 [%0], %1;" :: "r"(a), "r"(c) : "memory")
#define MBAR_EXPECT(a, n) \
    asm volatile("mbarrier.arrive.expect_tx.shared.b64 _, [%0], %1;" :: "r"(a), "r"(n) : "memory")
__device__ __forceinline__ void mbar_wait(uint32_t a, uint32_t parity) {
    asm volatile(
        "{ .reg .pred P;\n"
        "W_%=: mbarrier.try_wait.parity.acquire.cta.shared::cta.b64 P, [%0], %1, 0x989680;\n"
        "@P bra.uni D_%=; bra.uni W_%=;\n"
        "D_%=: }" :: "r"(a), "r"(parity) : "memory");
}
__device__ __forceinline__ void bulk_g2s(uint32_t dst, const void* src,
                                         uint32_t bytes, uint32_t mbar) {
    asm volatile(
        "cp.async.bulk.shared::cluster.global.mbarrier::complete_tx::bytes "
        "[%0], [%1], %2, [%3];"
        :: "r"(dst), "l"(src), "r"(bytes), "r"(mbar) : "memory");
}

__device__ __forceinline__ uint32_t tf32_rna(float x) {
    uint32_t r;
    asm("cvt.rna.tf32.f32 %0, %1;" : "=r"(r) : "f"(x));
    return r;
}
__device__ __forceinline__ void split_tf32(float x, uint32_t& hi, uint32_t& lo) {
    hi = tf32_rna(x);
    lo = tf32_rna(x - __uint_as_float(hi));
}
__device__ __forceinline__ void mma_tf32(float* d, const uint32_t* a,
                                         uint32_t b0, uint32_t b1) {
    asm volatile(
        "mma.sync.aligned.m16n8k8.row.col.f32.tf32.tf32.f32 "
        "{%0,%1,%2,%3}, {%4,%5,%6,%7}, {%8,%9}, {%0,%1,%2,%3};"
        : "+f"(d[0]), "+f"(d[1]), "+f"(d[2]), "+f"(d[3])
        : "r"(a[0]), "r"(a[1]), "r"(a[2]), "r"(a[3]), "r"(b0), "r"(b1));
}

// ---------------------------------------------------------------------------
// Kernel 1: transpose x [B, C_IN, N] -> xt [B, N, C_IN]
// Tile = 32 channels x 128 nodes. float2 loads (rows only 8B-aligned since
// NNODE % 4 == 2), float4 stores (xt rows are 128B-aligned).
// FIX vs R9: store phase covers all 128 nodes (4 passes, was 2).
// ---------------------------------------------------------------------------
__global__ __launch_bounds__(256) void transpose_kernel(const float* __restrict__ x,
                                                        float* __restrict__ xt) {
    __shared__ float2 t2[32][65];          // pitch 65 (odd) float2
    const int b  = blockIdx.y;
    const int n0 = blockIdx.x * 128;
    const int tid = threadIdx.x;

    // Load: thread covers (c = tid>>5 + 8k, col2 = tid&31 + 32h).
#pragma unroll
    for (int k = 0; k < 4; k++) {
#pragma unroll
        for (int h = 0; h < 2; h++) {
            const int c  = (tid >> 5) + 8 * k;
            const int c2 = (tid & 31) + 32 * h;
            const int n  = n0 + 2 * c2;
            const float* xr = x + ((size_t)b * C_IN + c) * NNODE;
            float2 v = make_float2(0.f, 0.f);
            if (n + 1 < NNODE)      v = *(const float2*)(xr + n);
            else if (n < NNODE)     v.x = xr[n];
            t2[c][c2] = v;
        }
    }
    __syncthreads();

    // Store: thread (u = tid&7, nn = tid>>3 + 32*pass), 4 passes cover nn 0..127.
    const float* tf = (const float*)t2;    // pitch 130 floats
#pragma unroll
    for (int pass = 0; pass < 4; pass++) {
        const int nn = (tid >> 3) + 32 * pass;
        const int n  = n0 + nn;
        if (n < NNODE) {
            const int cb = 4 * (tid & 7);
            float4 o;
            o.x = tf[(cb + 0) * 130 + nn];
            o.y = tf[(cb + 1) * 130 + nn];
            o.z = tf[(cb + 2) * 130 + nn];
            o.w = tf[(cb + 3) * 130 + nn];
            *(float4*)(xt + ((size_t)b * NNODE + n) * C_IN + cb) = o;
        }
    }
}

// Kernel 1b: split W [32][224] into fragment-ordered images, hi/lo interleaved.
__global__ __launch_bounds__(256) void wsplit_kernel(const float* __restrict__ W,
                                                     float* __restrict__ wimg) {
    const int i = blockIdx.x * 256 + threadIdx.x;
    if (i >= 32 * 224) return;
    const int o = i / 224, k = i % 224;
    const int j = k / 32, kk = k % 32;
    const int ks = kk >> 3, kc = kk & 7;
    const int nb = o >> 3;
    const int lane = (o & 7) * 4 + (kc & 3);
    const int reg = kc >> 2;
    uint32_t hb, lb;
    split_tf32(W[i], hb, lb);
    const int base = ((j * 16 + ks * 4 + nb) * 32 + lane) * 4;
    wimg[base + reg]     = __uint_as_float(hb);
    wimg[base + 2 + reg] = __uint_as_float(lb);
}

// ---------------------------------------------------------------------------
// Kernel 2: mma.sync tf32 conv, 3-term hi/lo split in registers.
// A rows gathered via cp.async.bulk (1x128B per row), W via one 56KB bulk.
// Double-buffered on two mbarriers.
// ---------------------------------------------------------------------------
__global__ __launch_bounds__(THREADS, 2) void onering_conv_mma_kernel(
    const float* __restrict__ xt,
    const int* __restrict__ neigh,
    const float* __restrict__ wimg,
    float* __restrict__ out) {

    extern __shared__ __align__(16) char smem[];
    const uint32_t sbase = s2u(smem);
    const uint32_t mb0 = sbase + SM_MBAR;
    const uint32_t mb1 = sbase + SM_MBAR + 8;

    const int tid  = threadIdx.x;
    const int wid  = tid >> 5;
    const int lane = tid & 31;
    const int b    = blockIdx.y;
    const int n0   = blockIdx.x * TM;

    // Neighbor indices for this thread's row -> registers.
    int mreg[K7];
    {
        const int nrow = n0 + tid;
        const int base = (nrow < NNODE) ? nrow * K7 : 0;
#pragma unroll
        for (int j = 0; j < K7; j++) mreg[j] = neigh[base + j];
    }

    if (tid == 0) { MBAR_INIT(mb0, 1); MBAR_INIT(mb1, 1); }
    __syncthreads();

    const float* xb = xt + (size_t)b * NNODE * C_IN;

    // Issue the 128B row copy for ring slot j into buffer buf.
    auto issue_rows = [&](int j, int buf) {
        const uint32_t dst = sbase + SM_A + buf * (TM * PITCH * 4)
                           + (uint32_t)tid * (PITCH * 4);
        bulk_g2s(dst, xb + (size_t)mreg[j] * C_IN, 128,
                 buf ? mb1 : mb0);
    };

    // Prologue: expect chunk0 (16KB) + W image (56KB) on mbar0, then issue.
    if (tid == 0) MBAR_EXPECT(mb0, 16384 + 57344);
    __syncthreads();
    if (tid == 0) bulk_g2s(sbase + SM_W, wimg, 57344, mb0);
    issue_rows(0, 0);

    float d[2][4][4];
#pragma unroll
    for (int mb = 0; mb < 2; mb++)
#pragma unroll
        for (int nb = 0; nb < 4; nb++)
#pragma unroll
            for (int q = 0; q < 4; q++) d[mb][nb][q] = 0.0f;

    const int g  = lane >> 2;
    const int c4 = lane & 3;

#pragma unroll 1
    for (int j = 0; j < K7; j++) {
        const int buf = j & 1;
        mbar_wait(buf ? mb1 : mb0, (j >> 1) & 1);

        if (j + 1 < K7 && tid == 0)
            MBAR_EXPECT(((j + 1) & 1) ? mb1 : mb0, 16384);
        __syncthreads();          // expect posted; all past wait; prior reads done
        if (j + 1 < K7) issue_rows(j + 1, (j + 1) & 1);

        // Load + split the 8 A fragments of chunk j.
        uint32_t ah[2][4][4], al[2][4][4];
        const uint32_t ab = sbase + SM_A + buf * (TM * PITCH * 4);
#pragma unroll
        for (int mb = 0; mb < 2; mb++) {
            const int rb = wid * 32 + mb * 16;
#pragma unroll
            for (int ks = 0; ks < 4; ks++) {
                const uint32_t a0 = ab + (uint32_t)(((rb + g) * PITCH + ks * 8 + c4) * 4);
                float r0, r1, r2, r3;
                asm("ld.shared.f32 %0, [%1];" : "=f"(r0) : "r"(a0));
                asm("ld.shared.f32 %0, [%1];" : "=f"(r2) : "r"(a0 + 16));
                asm("ld.shared.f32 %0, [%1];" : "=f"(r1) : "r"(a0 + 8 * PITCH * 4));
                asm("ld.shared.f32 %0, [%1];" : "=f"(r3) : "r"(a0 + 8 * PITCH * 4 + 16));
                split_tf32(r0, ah[mb][ks][0], al[mb][ks][0]);
                split_tf32(r1, ah[mb][ks][1], al[mb][ks][1]);
                split_tf32(r2, ah[mb][ks][2], al[mb][ks][2]);
                split_tf32(r3, ah[mb][ks][3], al[mb][ks][3]);
            }
        }
        __syncthreads();          // reads of buf done before j+2 overwrites it

        // MMA with W chunk j (one LDS.128 per (ks, nb)).
        const uint32_t wbase = sbase + SM_W + (uint32_t)(j * 16 * 32 * 16);
#pragma unroll
        for (int ks = 0; ks < 4; ks++) {
#pragma unroll
            for (int nb = 0; nb < 4; nb++) {
                uint32_t w0, w1, w2, w3;
                asm("ld.shared.v4.b32 {%0,%1,%2,%3}, [%4];"
                    : "=r"(w0), "=r"(w1), "=r"(w2), "=r"(w3)
                    : "r"(wbase + (uint32_t)(((ks * 4 + nb) * 32 + lane) * 16)));
#pragma unroll
                for (int mb = 0; mb < 2; mb++) {
                    mma_tf32(d[mb][nb], ah[mb][ks], w0, w1);
                    mma_tf32(d[mb][nb], al[mb][ks], w0, w1);
                    mma_tf32(d[mb][nb], ah[mb][ks], w2, w3);
                }
            }
        }
    }

    // Epilogue.
    const int r_lo = lane >> 2;
    const int c0   = 2 * (lane & 3);
#pragma unroll
    for (int mb = 0; mb < 2; mb++) {
        const int nrow = n0 + wid * 32 + mb * 16;
#pragma unroll
        for (int nb = 0; nb < 4; nb++) {
            const int o = nb * 8 + c0;
#pragma unroll
            for (int half = 0; half < 2; half++) {
                const int n = nrow + r_lo + half * 8;
                if (n < NNODE) {
                    float* ob = out + (size_t)b * C_OUT * NNODE + n;
                    ob[(size_t)o * NNODE]       = d[mb][nb][half * 2]     + cB[o];
                    ob[(size_t)(o + 1) * NNODE] = d[mb][nb][half * 2 + 1] + cB[o + 1];
                }
            }
        }
    }
}

// ---------------------------------------------------------------------------
// Launch
// ---------------------------------------------------------------------------
extern "C" void kernel_launch(void* const* d_in, const int* in_sizes, int n_in,
                              void* d_out, int out_size) {
    const float* x     = (const float*)d_in[0];
    const float* W     = (const float*)d_in[1];
    const float* bias  = (const float*)d_in[2];
    const int*   neigh = (const int*)d_in[3];
    float* out = (float*)d_out;

    float* xt = nullptr;
    cudaGetSymbolAddress((void**)&xt, g_xt);
    float* wimg = nullptr;
    cudaGetSymbolAddress((void**)&wimg, g_wimg);

    {
        dim3 grid((NNODE + 127) / 128, BATCH);
        transpose_kernel<<<grid, 256>>>(x, xt);
    }
    wsplit_kernel<<<(32 * 224 + 255) / 256, 256>>>(W, wimg);
    cudaMemcpyToSymbolAsync(cB, bias, C_OUT * sizeof(float), 0,
                            cudaMemcpyDeviceToDevice, 0);
    {
        cudaFuncSetAttribute(onering_conv_mma_kernel,
                             cudaFuncAttributeMaxDynamicSharedMemorySize, SM_TOTAL);
        dim3 grid(NT2, BATCH);
        onering_conv_mma_kernel<<<grid, THREADS, SM_TOTAL>>>(xt, neigh, wimg, out);
    }
}

// round 11
// speedup vs baseline: 1.3919x; 1.3919x over previous
#include <cuda_runtime.h>
#include <cstdint>

#define BATCH 4
#define C_IN 32
#define C_OUT 32
#define NNODE 163842
#define K7 7

#define TM 128                           // nodes per CTA
#define THREADS 128                      // 4 warps
#define NT2 ((NNODE + TM - 1) / TM)      // 1281
#define PITCH 36                         // A row pitch in floats (144B)

// ---- global scratch ----
__device__ float g_xt[(size_t)BATCH * NNODE * C_IN];   // x transposed [B,N,32]
// W fragment images, hi/lo interleaved per 16B: [j][ks][nb][lane][bh0 bh1 bl0 bl1]
__device__ float g_wimg[K7 * 16 * 32 * 4];             // 14336 floats = 56KB
__constant__ float cB[C_OUT];

// ---- smem layout (bytes) ----
#define SM_A     0                        // 2 bufs x TM x PITCH x 4 = 36864
#define SM_W     36864                    // 57344
#define SM_SIDX  94208                    // 128*7 ints = 3584
#define SM_TOTAL 97792

// ---------------------------------------------------------------------------
// helpers
// ---------------------------------------------------------------------------
__device__ __forceinline__ uint32_t s2u(const void* p) {
    uint32_t a;
    asm("{ .reg .u64 t; cvta.to.shared.u64 t, %1; cvt.u32.u64 %0, t; }"
        : "=r"(a) : "l"(p));
    return a;
}
#define CP_ASYNC16(d, s) asm volatile("cp.async.cg.shared.global [%0], [%1], 16;" :: "r"(d), "l"(s))
#define CP_COMMIT()      asm volatile("cp.async.commit_group;")
#define CP_WAIT(n)       asm volatile("cp.async.wait_group %0;" :: "n"(n))

__device__ __forceinline__ uint32_t tf32_rna(float x) {
    uint32_t r;
    asm("cvt.rna.tf32.f32 %0, %1;" : "=r"(r) : "f"(x));
    return r;
}
__device__ __forceinline__ void split_tf32(float x, uint32_t& hi, uint32_t& lo) {
    hi = tf32_rna(x);
    lo = tf32_rna(x - __uint_as_float(hi));
}
__device__ __forceinline__ void mma_tf32(float* d, const uint32_t* a,
                                         uint32_t b0, uint32_t b1) {
    asm volatile(
        "mma.sync.aligned.m16n8k8.row.col.f32.tf32.tf32.f32 "
        "{%0,%1,%2,%3}, {%4,%5,%6,%7}, {%8,%9}, {%0,%1,%2,%3};"
        : "+f"(d[0]), "+f"(d[1]), "+f"(d[2]), "+f"(d[3])
        : "r"(a[0]), "r"(a[1]), "r"(a[2]), "r"(a[3]), "r"(b0), "r"(b1));
}

// ---------------------------------------------------------------------------
// Kernel 1: transpose x [B, C_IN, N] -> xt [B, N, C_IN]  (R10 version, 23.8us)
// ---------------------------------------------------------------------------
__global__ __launch_bounds__(256) void transpose_kernel(const float* __restrict__ x,
                                                        float* __restrict__ xt) {
    __shared__ float2 t2[32][65];          // pitch 65 (odd) float2
    const int b  = blockIdx.y;
    const int n0 = blockIdx.x * 128;
    const int tid = threadIdx.x;

#pragma unroll
    for (int k = 0; k < 4; k++) {
#pragma unroll
        for (int h = 0; h < 2; h++) {
            const int c  = (tid >> 5) + 8 * k;
            const int c2 = (tid & 31) + 32 * h;
            const int n  = n0 + 2 * c2;
            const float* xr = x + ((size_t)b * C_IN + c) * NNODE;
            float2 v = make_float2(0.f, 0.f);
            if (n + 1 < NNODE)      v = *(const float2*)(xr + n);
            else if (n < NNODE)     v.x = xr[n];
            t2[c][c2] = v;
        }
    }
    __syncthreads();

    const float* tf = (const float*)t2;    // pitch 130 floats
#pragma unroll
    for (int pass = 0; pass < 4; pass++) {
        const int nn = (tid >> 3) + 32 * pass;
        const int n  = n0 + nn;
        if (n < NNODE) {
            const int cb = 4 * (tid & 7);
            float4 o;
            o.x = tf[(cb + 0) * 130 + nn];
            o.y = tf[(cb + 1) * 130 + nn];
            o.z = tf[(cb + 2) * 130 + nn];
            o.w = tf[(cb + 3) * 130 + nn];
            *(float4*)(xt + ((size_t)b * NNODE + n) * C_IN + cb) = o;
        }
    }
}

// Kernel 1b: split W [32][224] into fragment-ordered images, hi/lo interleaved.
__global__ __launch_bounds__(256) void wsplit_kernel(const float* __restrict__ W,
                                                     float* __restrict__ wimg) {
    const int i = blockIdx.x * 256 + threadIdx.x;
    if (i >= 32 * 224) return;
    const int o = i / 224, k = i % 224;
    const int j = k / 32, kk = k % 32;
    const int ks = kk >> 3, kc = kk & 7;
    const int nb = o >> 3;
    const int lane = (o & 7) * 4 + (kc & 3);
    const int reg = kc >> 2;
    uint32_t hb, lb;
    split_tf32(W[i], hb, lb);
    const int base = ((j * 16 + ks * 4 + nb) * 32 + lane) * 4;
    wimg[base + reg]     = __uint_as_float(hb);
    wimg[base + 2 + reg] = __uint_as_float(lb);
}

// ---------------------------------------------------------------------------
// Kernel 2: mma.sync tf32 conv (R8 version, ~175us), 3-term hi/lo in registers.
// A gathered row-major via 16B cp.async; W images static in smem.
// ---------------------------------------------------------------------------
__global__ __launch_bounds__(THREADS, 2) void onering_conv_mma_kernel(
    const float* __restrict__ xt,
    const int* __restrict__ neigh,
    const float* __restrict__ wimg,
    float* __restrict__ out) {

    extern __shared__ __align__(16) char smem[];
    const uint32_t sbase = s2u(smem);
    int* sidx = (int*)(smem + SM_SIDX);

    const int tid  = threadIdx.x;
    const int wid  = tid >> 5;
    const int lane = tid & 31;
    const int b    = blockIdx.y;
    const int n0   = blockIdx.x * TM;

#pragma unroll
    for (int i = tid; i < TM * K7; i += THREADS) {
        const int gg = n0 * K7 + i;
        sidx[i] = (gg < NNODE * K7) ? neigh[gg] : 0;
    }
    __syncthreads();

    const float* xb = xt + (size_t)b * NNODE * C_IN;
    const int rsub = lane >> 3, seg = lane & 7;

    auto gather = [&](int j, int buf) {
        const uint32_t abase = sbase + SM_A + buf * (TM * PITCH * 4);
#pragma unroll
        for (int it = 0; it < 8; it++) {
            const int r = it * 16 + wid * 4 + rsub;
            const int m = sidx[r * K7 + j];
            CP_ASYNC16(abase + (uint32_t)(r * (PITCH * 4) + seg * 16),
                       xb + (size_t)m * C_IN + seg * 4);
        }
    };

    // Prologue: W images (56KB) + first gather in one cp.async group.
#pragma unroll
    for (int i = tid; i < 3584; i += THREADS)
        CP_ASYNC16(sbase + SM_W + i * 16, wimg + i * 4);
    gather(0, 0);
    CP_COMMIT();

    float d[2][4][4];
#pragma unroll
    for (int mb = 0; mb < 2; mb++)
#pragma unroll
        for (int nb = 0; nb < 4; nb++)
#pragma unroll
            for (int q = 0; q < 4; q++) d[mb][nb][q] = 0.0f;

    const int g  = lane >> 2;
    const int c4 = lane & 3;

#pragma unroll 1
    for (int j = 0; j < K7; j++) {
        const int buf = j & 1;
        if (j + 1 < K7) {
            gather(j + 1, buf ^ 1);
            CP_COMMIT();
            CP_WAIT(1);
        } else {
            CP_WAIT(0);
        }
        __syncthreads();

        // Load + split the 8 A fragments of chunk j.
        uint32_t ah[2][4][4], al[2][4][4];
        const uint32_t ab = sbase + SM_A + buf * (TM * PITCH * 4);
#pragma unroll
        for (int mb = 0; mb < 2; mb++) {
            const int rb = wid * 32 + mb * 16;
#pragma unroll
            for (int ks = 0; ks < 4; ks++) {
                const uint32_t a0 = ab + (uint32_t)(((rb + g) * PITCH + ks * 8 + c4) * 4);
                float r0, r1, r2, r3;
                asm("ld.shared.f32 %0, [%1];" : "=f"(r0) : "r"(a0));
                asm("ld.shared.f32 %0, [%1];" : "=f"(r2) : "r"(a0 + 16));
                asm("ld.shared.f32 %0, [%1];" : "=f"(r1) : "r"(a0 + 8 * PITCH * 4));
                asm("ld.shared.f32 %0, [%1];" : "=f"(r3) : "r"(a0 + 8 * PITCH * 4 + 16));
                split_tf32(r0, ah[mb][ks][0], al[mb][ks][0]);
                split_tf32(r1, ah[mb][ks][1], al[mb][ks][1]);
                split_tf32(r2, ah[mb][ks][2], al[mb][ks][2]);
                split_tf32(r3, ah[mb][ks][3], al[mb][ks][3]);
            }
        }
        __syncthreads();

        // MMA with W chunk j (one LDS.128 per (ks, nb)).
        const uint32_t wbase = sbase + SM_W + (uint32_t)(j * 16 * 32 * 16);
#pragma unroll
        for (int ks = 0; ks < 4; ks++) {
#pragma unroll
            for (int nb = 0; nb < 4; nb++) {
                uint32_t w0, w1, w2, w3;
                asm("ld.shared.v4.b32 {%0,%1,%2,%3}, [%4];"
                    : "=r"(w0), "=r"(w1), "=r"(w2), "=r"(w3)
                    : "r"(wbase + (uint32_t)(((ks * 4 + nb) * 32 + lane) * 16)));
#pragma unroll
                for (int mb = 0; mb < 2; mb++) {
                    mma_tf32(d[mb][nb], ah[mb][ks], w0, w1);
                    mma_tf32(d[mb][nb], al[mb][ks], w0, w1);
                    mma_tf32(d[mb][nb], ah[mb][ks], w2, w3);
                }
            }
        }
    }

    // Epilogue.
    const int r_lo = lane >> 2;
    const int c0   = 2 * (lane & 3);
#pragma unroll
    for (int mb = 0; mb < 2; mb++) {
        const int nrow = n0 + wid * 32 + mb * 16;
#pragma unroll
        for (int nb = 0; nb < 4; nb++) {
            const int o = nb * 8 + c0;
#pragma unroll
            for (int half = 0; half < 2; half++) {
                const int n = nrow + r_lo + half * 8;
                if (n < NNODE) {
                    float* ob = out + (size_t)b * C_OUT * NNODE + n;
                    ob[(size_t)o * NNODE]       = d[mb][nb][half * 2]     + cB[o];
                    ob[(size_t)(o + 1) * NNODE] = d[mb][nb][half * 2 + 1] + cB[o + 1];
                }
            }
        }
    }
}

// ---------------------------------------------------------------------------
// Launch
// ---------------------------------------------------------------------------
extern "C" void kernel_launch(void* const* d_in, const int* in_sizes, int n_in,
                              void* d_out, int out_size) {
    const float* x     = (const float*)d_in[0];
    const float* W     = (const float*)d_in[1];
    const float* bias  = (const float*)d_in[2];
    const int*   neigh = (const int*)d_in[3];
    float* out = (float*)d_out;

    float* xt = nullptr;
    cudaGetSymbolAddress((void**)&xt, g_xt);
    float* wimg = nullptr;
    cudaGetSymbolAddress((void**)&wimg, g_wimg);

    {
        dim3 grid((NNODE + 127) / 128, BATCH);
        transpose_kernel<<<grid, 256>>>(x, xt);
    }
    wsplit_kernel<<<(32 * 224 + 255) / 256, 256>>>(W, wimg);
    cudaMemcpyToSymbolAsync(cB, bias, C_OUT * sizeof(float), 0,
                            cudaMemcpyDeviceToDevice, 0);
    {
        cudaFuncSetAttribute(onering_conv_mma_kernel,
                             cudaFuncAttributeMaxDynamicSharedMemorySize, SM_TOTAL);
        dim3 grid(NT2, BATCH);
        onering_conv_mma_kernel<<<grid, THREADS, SM_TOTAL>>>(xt, neigh, wimg, out);
    }
}

// round 12
// speedup vs baseline: 1.5365x; 1.1039x over previous
#include <cuda_runtime.h>
#include <cstdint>

#define BATCH 4
#define C_IN 32
#define C_OUT 32
#define NNODE 163842
#define K7 7

#define TM 128                           // nodes per CTA
#define THREADS 128                      // 4 warps
#define NT2 ((NNODE + TM - 1) / TM)      // 1281
#define PITCH 36                         // A row pitch in floats (144B)

// ---- global scratch ----
__device__ float g_xt[(size_t)BATCH * NNODE * C_IN];   // x transposed [B,N,32]
// W fragment images, hi/lo interleaved per 16B: [j][ks][nb][lane][bh0 bh1 bl0 bl1]
__device__ float g_wimg[K7 * 16 * 32 * 4];             // 14336 floats = 56KB
__constant__ float cB[C_OUT];

// ---- smem layout (bytes) ----
#define SM_A     0                        // 2 bufs x TM x PITCH x 4 = 36864
#define SM_W     36864                    // 57344
#define SM_SIDX  94208                    // 128*7 ints = 3584
#define SM_TOTAL 97792

// ---------------------------------------------------------------------------
// helpers
// ---------------------------------------------------------------------------
__device__ __forceinline__ uint32_t s2u(const void* p) {
    uint32_t a;
    asm("{ .reg .u64 t; cvta.to.shared.u64 t, %1; cvt.u32.u64 %0, t; }"
        : "=r"(a) : "l"(p));
    return a;
}
#define CP_ASYNC16(d, s) asm volatile("cp.async.cg.shared.global [%0], [%1], 16;" :: "r"(d), "l"(s))
#define CP_COMMIT()      asm volatile("cp.async.commit_group;")
#define CP_WAIT(n)       asm volatile("cp.async.wait_group %0;" :: "n"(n))

// CUTLASS-style mask split: HMMA.tf32 reads only the top 19 bits of the
// operand register, so hi = x & 0xFFFFE000 (exact tf32 value) and
// lo = x - hi passed RAW (hardware truncates lo's tail, ~2^-20 rel error).
__device__ __forceinline__ void split_tf32(float x, uint32_t& hi, uint32_t& lo) {
    hi = __float_as_uint(x) & 0xFFFFE000u;
    lo = __float_as_uint(x - __uint_as_float(hi));
}
__device__ __forceinline__ void mma_tf32(float* d, const uint32_t* a,
                                         uint32_t b0, uint32_t b1) {
    asm volatile(
        "mma.sync.aligned.m16n8k8.row.col.f32.tf32.tf32.f32 "
        "{%0,%1,%2,%3}, {%4,%5,%6,%7}, {%8,%9}, {%0,%1,%2,%3};"
        : "+f"(d[0]), "+f"(d[1]), "+f"(d[2]), "+f"(d[3])
        : "r"(a[0]), "r"(a[1]), "r"(a[2]), "r"(a[3]), "r"(b0), "r"(b1));
}

// ---------------------------------------------------------------------------
// Kernel 1: transpose x [B, C_IN, N] -> xt [B, N, C_IN]; block (0,0) also
// builds the W fragment images (merged wsplit).
// ---------------------------------------------------------------------------
__global__ __launch_bounds__(256) void transpose_kernel(const float* __restrict__ x,
                                                        const float* __restrict__ W,
                                                        float* __restrict__ xt,
                                                        float* __restrict__ wimg) {
    __shared__ float2 t2[32][65];          // pitch 65 (odd) float2
    const int b  = blockIdx.y;
    const int n0 = blockIdx.x * 128;
    const int tid = threadIdx.x;

#pragma unroll
    for (int k = 0; k < 4; k++) {
#pragma unroll
        for (int h = 0; h < 2; h++) {
            const int c  = (tid >> 5) + 8 * k;
            const int c2 = (tid & 31) + 32 * h;
            const int n  = n0 + 2 * c2;
            const float* xr = x + ((size_t)b * C_IN + c) * NNODE;
            float2 v = make_float2(0.f, 0.f);
            if (n + 1 < NNODE)      v = *(const float2*)(xr + n);
            else if (n < NNODE)     v.x = xr[n];
            t2[c][c2] = v;
        }
    }
    __syncthreads();

    const float* tf = (const float*)t2;    // pitch 130 floats
#pragma unroll
    for (int pass = 0; pass < 4; pass++) {
        const int nn = (tid >> 3) + 32 * pass;
        const int n  = n0 + nn;
        if (n < NNODE) {
            const int cb = 4 * (tid & 7);
            float4 o;
            o.x = tf[(cb + 0) * 130 + nn];
            o.y = tf[(cb + 1) * 130 + nn];
            o.z = tf[(cb + 2) * 130 + nn];
            o.w = tf[(cb + 3) * 130 + nn];
            *(float4*)(xt + ((size_t)b * NNODE + n) * C_IN + cb) = o;
        }
    }

    // Merged wsplit: block (0,0) builds fragment-ordered W images.
    if (blockIdx.x == 0 && blockIdx.y == 0) {
        for (int i = tid; i < 32 * 224; i += 256) {
            const int o = i / 224, k = i % 224;
            const int j = k / 32, kk = k % 32;
            const int ks = kk >> 3, kc = kk & 7;
            const int nb = o >> 3;
            const int lane = (o & 7) * 4 + (kc & 3);
            const int reg = kc >> 2;
            uint32_t hb, lb;
            split_tf32(W[i], hb, lb);
            const int base = ((j * 16 + ks * 4 + nb) * 32 + lane) * 4;
            wimg[base + reg]     = __uint_as_float(hb);
            wimg[base + 2 + reg] = __uint_as_float(lb);
        }
    }
}

// ---------------------------------------------------------------------------
// Kernel 2: mma.sync tf32 conv, 3-term mask-split in registers.
// A gathered row-major via 16B cp.async; W images static in smem.
// ---------------------------------------------------------------------------
__global__ __launch_bounds__(THREADS, 2) void onering_conv_mma_kernel(
    const float* __restrict__ xt,
    const int* __restrict__ neigh,
    const float* __restrict__ wimg,
    float* __restrict__ out) {

    extern __shared__ __align__(16) char smem[];
    const uint32_t sbase = s2u(smem);
    int* sidx = (int*)(smem + SM_SIDX);

    const int tid  = threadIdx.x;
    const int wid  = tid >> 5;
    const int lane = tid & 31;
    const int b    = blockIdx.y;
    const int n0   = blockIdx.x * TM;

#pragma unroll
    for (int i = tid; i < TM * K7; i += THREADS) {
        const int gg = n0 * K7 + i;
        sidx[i] = (gg < NNODE * K7) ? neigh[gg] : 0;
    }
    __syncthreads();

    const float* xb = xt + (size_t)b * NNODE * C_IN;
    const int rsub = lane >> 3, seg = lane & 7;

    auto gather = [&](int j, int buf) {
        const uint32_t abase = sbase + SM_A + buf * (TM * PITCH * 4);
#pragma unroll
        for (int it = 0; it < 8; it++) {
            const int r = it * 16 + wid * 4 + rsub;
            const int m = sidx[r * K7 + j];
            CP_ASYNC16(abase + (uint32_t)(r * (PITCH * 4) + seg * 16),
                       xb + (size_t)m * C_IN + seg * 4);
        }
    };

    // Prologue: W images (56KB) + first gather in one cp.async group.
#pragma unroll
    for (int i = tid; i < 3584; i += THREADS)
        CP_ASYNC16(sbase + SM_W + i * 16, wimg + i * 4);
    gather(0, 0);
    CP_COMMIT();

    float d[2][4][4];
#pragma unroll
    for (int mb = 0; mb < 2; mb++)
#pragma unroll
        for (int nb = 0; nb < 4; nb++)
#pragma unroll
            for (int q = 0; q < 4; q++) d[mb][nb][q] = 0.0f;

    const int g  = lane >> 2;
    const int c4 = lane & 3;

#pragma unroll 1
    for (int j = 0; j < K7; j++) {
        const int buf = j & 1;
        if (j + 1 < K7) {
            gather(j + 1, buf ^ 1);
            CP_COMMIT();
            CP_WAIT(1);
        } else {
            CP_WAIT(0);
        }
        __syncthreads();

        // Load + mask-split the 8 A fragments of chunk j.
        uint32_t ah[2][4][4], al[2][4][4];
        const uint32_t ab = sbase + SM_A + buf * (TM * PITCH * 4);
#pragma unroll
        for (int mb = 0; mb < 2; mb++) {
            const int rb = wid * 32 + mb * 16;
#pragma unroll
            for (int ks = 0; ks < 4; ks++) {
                const uint32_t a0 = ab + (uint32_t)(((rb + g) * PITCH + ks * 8 + c4) * 4);
                float r0, r1, r2, r3;
                asm("ld.shared.f32 %0, [%1];" : "=f"(r0) : "r"(a0));
                asm("ld.shared.f32 %0, [%1];" : "=f"(r2) : "r"(a0 + 16));
                asm("ld.shared.f32 %0, [%1];" : "=f"(r1) : "r"(a0 + 8 * PITCH * 4));
                asm("ld.shared.f32 %0, [%1];" : "=f"(r3) : "r"(a0 + 8 * PITCH * 4 + 16));
                split_tf32(r0, ah[mb][ks][0], al[mb][ks][0]);
                split_tf32(r1, ah[mb][ks][1], al[mb][ks][1]);
                split_tf32(r2, ah[mb][ks][2], al[mb][ks][2]);
                split_tf32(r3, ah[mb][ks][3], al[mb][ks][3]);
            }
        }
        __syncthreads();

        // MMA with W chunk j (one LDS.128 per (ks, nb)).
        const uint32_t wbase = sbase + SM_W + (uint32_t)(j * 16 * 32 * 16);
#pragma unroll
        for (int ks = 0; ks < 4; ks++) {
#pragma unroll
            for (int nb = 0; nb < 4; nb++) {
                uint32_t w0, w1, w2, w3;
                asm("ld.shared.v4.b32 {%0,%1,%2,%3}, [%4];"
                    : "=r"(w0), "=r"(w1), "=r"(w2), "=r"(w3)
                    : "r"(wbase + (uint32_t)(((ks * 4 + nb) * 32 + lane) * 16)));
#pragma unroll
                for (int mb = 0; mb < 2; mb++) {
                    mma_tf32(d[mb][nb], ah[mb][ks], w0, w1);
                    mma_tf32(d[mb][nb], al[mb][ks], w0, w1);
                    mma_tf32(d[mb][nb], ah[mb][ks], w2, w3);
                }
            }
        }
    }

    // Epilogue.
    const int r_lo = lane >> 2;
    const int c0   = 2 * (lane & 3);
#pragma unroll
    for (int mb = 0; mb < 2; mb++) {
        const int nrow = n0 + wid * 32 + mb * 16;
#pragma unroll
        for (int nb = 0; nb < 4; nb++) {
            const int o = nb * 8 + c0;
#pragma unroll
            for (int half = 0; half < 2; half++) {
                const int n = nrow + r_lo + half * 8;
                if (n < NNODE) {
                    float* ob = out + (size_t)b * C_OUT * NNODE + n;
                    ob[(size_t)o * NNODE]       = d[mb][nb][half * 2]     + cB[o];
                    ob[(size_t)(o + 1) * NNODE] = d[mb][nb][half * 2 + 1] + cB[o + 1];
                }
            }
        }
    }
}

// ---------------------------------------------------------------------------
// Launch
// ---------------------------------------------------------------------------
extern "C" void kernel_launch(void* const* d_in, const int* in_sizes, int n_in,
                              void* d_out, int out_size) {
    const float* x     = (const float*)d_in[0];
    const float* W     = (const float*)d_in[1];
    const float* bias  = (const float*)d_in[2];
    const int*   neigh = (const int*)d_in[3];
    float* out = (float*)d_out;

    float* xt = nullptr;
    cudaGetSymbolAddress((void**)&xt, g_xt);
    float* wimg = nullptr;
    cudaGetSymbolAddress((void**)&wimg, g_wimg);

    {
        dim3 grid((NNODE + 127) / 128, BATCH);
        transpose_kernel<<<grid, 256>>>(x, W, xt, wimg);
    }
    cudaMemcpyToSymbolAsync(cB, bias, C_OUT * sizeof(float), 0,
                            cudaMemcpyDeviceToDevice, 0);
    {
        cudaFuncSetAttribute(onering_conv_mma_kernel,
                             cudaFuncAttributeMaxDynamicSharedMemorySize, SM_TOTAL);
        dim3 grid(NT2, BATCH);
        onering_conv_mma_kernel<<<grid, THREADS, SM_TOTAL>>>(xt, neigh, wimg, out);
    }
}

// round 13
// speedup vs baseline: 1.6588x; 1.0796x over previous
#include <cuda_runtime.h>
#include <cstdint>

#define BATCH 4
#define C_IN 32
#define C_OUT 32
#define NNODE 163842
#define K7 7

#define TM 128                           // nodes per CTA
#define THREADS 128                      // 4 warps
#define NT2 ((NNODE + TM - 1) / TM)      // 1281
#define PITCH 36                         // A row pitch in floats (144B)

// ---- global scratch ----
__device__ float g_xt[(size_t)BATCH * NNODE * C_IN];   // x transposed [B,N,32]
// W fragment images, hi/lo interleaved per 16B: [j][ks][nb][lane][bh0 bh1 bl0 bl1]
__device__ float g_wimg[K7 * 16 * 32 * 4];             // 14336 floats = 56KB
__constant__ float cB[C_OUT];

// ---- smem layout (bytes) ----
#define SM_A     0                        // 2 bufs x TM x PITCH x 4 = 36864
#define SM_SIDX  36864                    // 128*7 ints = 3584
#define SM_TOTAL 40448

// ---------------------------------------------------------------------------
// helpers
// ---------------------------------------------------------------------------
__device__ __forceinline__ uint32_t s2u(const void* p) {
    uint32_t a;
    asm("{ .reg .u64 t; cvta.to.shared.u64 t, %1; cvt.u32.u64 %0, t; }"
        : "=r"(a) : "l"(p));
    return a;
}
#define CP_ASYNC16(d, s) asm volatile("cp.async.cg.shared.global [%0], [%1], 16;" :: "r"(d), "l"(s))
#define CP_COMMIT()      asm volatile("cp.async.commit_group;")
#define CP_WAIT(n)       asm volatile("cp.async.wait_group %0;" :: "n"(n))

// CUTLASS-style mask split: HMMA.tf32 reads only the top 19 bits of the
// operand register, so hi = x & 0xFFFFE000 and lo = x - hi passed raw.
__device__ __forceinline__ void split_tf32(float x, uint32_t& hi, uint32_t& lo) {
    hi = __float_as_uint(x) & 0xFFFFE000u;
    lo = __float_as_uint(x - __uint_as_float(hi));
}
__device__ __forceinline__ void mma_tf32(float* d, const uint32_t* a,
                                         uint32_t b0, uint32_t b1) {
    asm volatile(
        "mma.sync.aligned.m16n8k8.row.col.f32.tf32.tf32.f32 "
        "{%0,%1,%2,%3}, {%4,%5,%6,%7}, {%8,%9}, {%0,%1,%2,%3};"
        : "+f"(d[0]), "+f"(d[1]), "+f"(d[2]), "+f"(d[3])
        : "r"(a[0]), "r"(a[1]), "r"(a[2]), "r"(a[3]), "r"(b0), "r"(b1));
}

// ---------------------------------------------------------------------------
// Kernel 1: transpose x [B, C_IN, N] -> xt [B, N, C_IN]; block (0,0) also
// builds the W fragment images (merged wsplit).
// ---------------------------------------------------------------------------
__global__ __launch_bounds__(256) void transpose_kernel(const float* __restrict__ x,
                                                        const float* __restrict__ W,
                                                        float* __restrict__ xt,
                                                        float* __restrict__ wimg) {
    __shared__ float2 t2[32][65];          // pitch 65 (odd) float2
    const int b  = blockIdx.y;
    const int n0 = blockIdx.x * 128;
    const int tid = threadIdx.x;

#pragma unroll
    for (int k = 0; k < 4; k++) {
#pragma unroll
        for (int h = 0; h < 2; h++) {
            const int c  = (tid >> 5) + 8 * k;
            const int c2 = (tid & 31) + 32 * h;
            const int n  = n0 + 2 * c2;
            const float* xr = x + ((size_t)b * C_IN + c) * NNODE;
            float2 v = make_float2(0.f, 0.f);
            if (n + 1 < NNODE)      v = *(const float2*)(xr + n);
            else if (n < NNODE)     v.x = xr[n];
            t2[c][c2] = v;
        }
    }
    __syncthreads();

    const float* tf = (const float*)t2;    // pitch 130 floats
#pragma unroll
    for (int pass = 0; pass < 4; pass++) {
        const int nn = (tid >> 3) + 32 * pass;
        const int n  = n0 + nn;
        if (n < NNODE) {
            const int cb = 4 * (tid & 7);
            float4 o;
            o.x = tf[(cb + 0) * 130 + nn];
            o.y = tf[(cb + 1) * 130 + nn];
            o.z = tf[(cb + 2) * 130 + nn];
            o.w = tf[(cb + 3) * 130 + nn];
            *(float4*)(xt + ((size_t)b * NNODE + n) * C_IN + cb) = o;
        }
    }

    // Merged wsplit: block (0,0) builds fragment-ordered W images.
    if (blockIdx.x == 0 && blockIdx.y == 0) {
        for (int i = tid; i < 32 * 224; i += 256) {
            const int o = i / 224, k = i % 224;
            const int j = k / 32, kk = k % 32;
            const int ks = kk >> 3, kc = kk & 7;
            const int nb = o >> 3;
            const int lane = (o & 7) * 4 + (kc & 3);
            const int reg = kc >> 2;
            uint32_t hb, lb;
            split_tf32(W[i], hb, lb);
            const int base = ((j * 16 + ks * 4 + nb) * 32 + lane) * 4;
            wimg[base + reg]     = __uint_as_float(hb);
            wimg[base + 2 + reg] = __uint_as_float(lb);
        }
    }
}

// ---------------------------------------------------------------------------
// Kernel 2: mma.sync tf32 conv, 3-term mask-split in registers.
// A gathered row-major via 16B cp.async (smem); W fragments read via LDG.128
// from gmem (L1/L2-resident, shared across all CTAs) -> smem 40.4KB ->
// 4 CTAs/SM (16 warps) instead of 2.
// ---------------------------------------------------------------------------
__global__ __launch_bounds__(THREADS, 4) void onering_conv_mma_kernel(
    const float* __restrict__ xt,
    const int* __restrict__ neigh,
    const float* __restrict__ wimg,
    float* __restrict__ out) {

    extern __shared__ __align__(16) char smem[];
    const uint32_t sbase = s2u(smem);
    int* sidx = (int*)(smem + SM_SIDX);

    const int tid  = threadIdx.x;
    const int wid  = tid >> 5;
    const int lane = tid & 31;
    const int b    = blockIdx.y;
    const int n0   = blockIdx.x * TM;

#pragma unroll
    for (int i = tid; i < TM * K7; i += THREADS) {
        const int gg = n0 * K7 + i;
        sidx[i] = (gg < NNODE * K7) ? neigh[gg] : 0;
    }
    __syncthreads();

    const float* xb = xt + (size_t)b * NNODE * C_IN;
    const int rsub = lane >> 3, seg = lane & 7;

    auto gather = [&](int j, int buf) {
        const uint32_t abase = sbase + SM_A + buf * (TM * PITCH * 4);
#pragma unroll
        for (int it = 0; it < 8; it++) {
            const int r = it * 16 + wid * 4 + rsub;
            const int m = sidx[r * K7 + j];
            CP_ASYNC16(abase + (uint32_t)(r * (PITCH * 4) + seg * 16),
                       xb + (size_t)m * C_IN + seg * 4);
        }
    };

    gather(0, 0);
    CP_COMMIT();

    float d[2][4][4];
#pragma unroll
    for (int mb = 0; mb < 2; mb++)
#pragma unroll
        for (int nb = 0; nb < 4; nb++)
#pragma unroll
            for (int q = 0; q < 4; q++) d[mb][nb][q] = 0.0f;

    const int g  = lane >> 2;
    const int c4 = lane & 3;
    // Per-lane W fragment base (float4 granularity): index (chunk-local) =
    // ((ks*4 + nb)*32 + lane); chunk stride = 512 float4... in floats *4.
    const float4* wbase4 = (const float4*)wimg + lane;

#pragma unroll 1
    for (int j = 0; j < K7; j++) {
        const int buf = j & 1;
        if (j + 1 < K7) {
            gather(j + 1, buf ^ 1);
            CP_COMMIT();
            CP_WAIT(1);
        } else {
            CP_WAIT(0);
        }
        __syncthreads();

        // Load + mask-split the 8 A fragments of chunk j.
        uint32_t ah[2][4][4], al[2][4][4];
        const uint32_t ab = sbase + SM_A + buf * (TM * PITCH * 4);
#pragma unroll
        for (int mb = 0; mb < 2; mb++) {
            const int rb = wid * 32 + mb * 16;
#pragma unroll
            for (int ks = 0; ks < 4; ks++) {
                const uint32_t a0 = ab + (uint32_t)(((rb + g) * PITCH + ks * 8 + c4) * 4);
                float r0, r1, r2, r3;
                asm("ld.shared.f32 %0, [%1];" : "=f"(r0) : "r"(a0));
                asm("ld.shared.f32 %0, [%1];" : "=f"(r2) : "r"(a0 + 16));
                asm("ld.shared.f32 %0, [%1];" : "=f"(r1) : "r"(a0 + 8 * PITCH * 4));
                asm("ld.shared.f32 %0, [%1];" : "=f"(r3) : "r"(a0 + 8 * PITCH * 4 + 16));
                split_tf32(r0, ah[mb][ks][0], al[mb][ks][0]);
                split_tf32(r1, ah[mb][ks][1], al[mb][ks][1]);
                split_tf32(r2, ah[mb][ks][2], al[mb][ks][2]);
                split_tf32(r3, ah[mb][ks][3], al[mb][ks][3]);
            }
        }
        __syncthreads();

        // MMA with W chunk j: fragments via coalesced LDG.128 (L1-resident).
        const float4* wj = wbase4 + (size_t)j * 512;
#pragma unroll
        for (int ks = 0; ks < 4; ks++) {
#pragma unroll
            for (int nb = 0; nb < 4; nb++) {
                const float4 wv = __ldg(wj + (ks * 4 + nb) * 32);
                const uint32_t w0 = __float_as_uint(wv.x);
                const uint32_t w1 = __float_as_uint(wv.y);
                const uint32_t w2 = __float_as_uint(wv.z);
                const uint32_t w3 = __float_as_uint(wv.w);
#pragma unroll
                for (int mb = 0; mb < 2; mb++) {
                    mma_tf32(d[mb][nb], ah[mb][ks], w0, w1);
                    mma_tf32(d[mb][nb], al[mb][ks], w0, w1);
                    mma_tf32(d[mb][nb], ah[mb][ks], w2, w3);
                }
            }
        }
    }

    // Epilogue.
    const int r_lo = lane >> 2;
    const int c0   = 2 * (lane & 3);
#pragma unroll
    for (int mb = 0; mb < 2; mb++) {
        const int nrow = n0 + wid * 32 + mb * 16;
#pragma unroll
        for (int nb = 0; nb < 4; nb++) {
            const int o = nb * 8 + c0;
#pragma unroll
            for (int half = 0; half < 2; half++) {
                const int n = nrow + r_lo + half * 8;
                if (n < NNODE) {
                    float* ob = out + (size_t)b * C_OUT * NNODE + n;
                    ob[(size_t)o * NNODE]       = d[mb][nb][half * 2]     + cB[o];
                    ob[(size_t)(o + 1) * NNODE] = d[mb][nb][half * 2 + 1] + cB[o + 1];
                }
            }
        }
    }
}

// ---------------------------------------------------------------------------
// Launch
// ---------------------------------------------------------------------------
extern "C" void kernel_launch(void* const* d_in, const int* in_sizes, int n_in,
                              void* d_out, int out_size) {
    const float* x     = (const float*)d_in[0];
    const float* W     = (const float*)d_in[1];
    const float* bias  = (const float*)d_in[2];
    const int*   neigh = (const int*)d_in[3];
    float* out = (float*)d_out;

    float* xt = nullptr;
    cudaGetSymbolAddress((void**)&xt, g_xt);
    float* wimg = nullptr;
    cudaGetSymbolAddress((void**)&wimg, g_wimg);

    {
        dim3 grid((NNODE + 127) / 128, BATCH);
        transpose_kernel<<<grid, 256>>>(x, W, xt, wimg);
    }
    cudaMemcpyToSymbolAsync(cB, bias, C_OUT * sizeof(float), 0,
                            cudaMemcpyDeviceToDevice, 0);
    {
        cudaFuncSetAttribute(onering_conv_mma_kernel,
                             cudaFuncAttributeMaxDynamicSharedMemorySize, SM_TOTAL);
        dim3 grid(NT2, BATCH);
        onering_conv_mma_kernel<<<grid, THREADS, SM_TOTAL>>>(xt, neigh, wimg, out);
    }
}

// round 14
// speedup vs baseline: 2.1068x; 1.2701x over previous
#include <cuda_runtime.h>
#include <cstdint>

#define BATCH 4
#define C_IN 32
#define C_OUT 32
#define NNODE 163842
#define K7 7

#define TM 128                           // nodes per CTA
#define THREADS 128                      // 4 warps
#define NT2 ((NNODE + TM - 1) / TM)      // 1281
#define PITCH 40                         // A row pitch in floats (160B)

// ---- global scratch ----
__device__ float g_xt[(size_t)BATCH * NNODE * C_IN];   // x transposed [B,N,32]
// W bf16 fragment images: [j][ks2*4+nb][lane] x {hi01, hi23, lo01, lo23}
__device__ float g_wimg[K7 * 8 * 32 * 4];              // 7168 floats = 28KB
__constant__ float cB[C_OUT];

// ---- smem layout (bytes) ----
#define SM_A     0                        // 2 bufs x TM x 160 = 40960
#define SM_SIDX  40960                    // 128*7 ints = 3584
#define SM_TOTAL 44544

// ---------------------------------------------------------------------------
// helpers
// ---------------------------------------------------------------------------
__device__ __forceinline__ uint32_t s2u(const void* p) {
    uint32_t a;
    asm("{ .reg .u64 t; cvta.to.shared.u64 t, %1; cvt.u32.u64 %0, t; }"
        : "=r"(a) : "l"(p));
    return a;
}
#define CP_ASYNC16(d, s) asm volatile("cp.async.cg.shared.global [%0], [%1], 16;" :: "r"(d), "l"(s))
#define CP_COMMIT()      asm volatile("cp.async.commit_group;")
#define CP_WAIT(n)       asm volatile("cp.async.wait_group %0;" :: "n"(n))

// bf16 hi/lo pack of a value pair: hi = top-16-bit truncation (exact fp32),
// lo = (x - hi) truncated to bf16. Result regs are bf16x2 {x, y}.
__device__ __forceinline__ void pack_pair(float x, float y,
                                          uint32_t& hi, uint32_t& lo) {
    const uint32_t bx = __float_as_uint(x), by = __float_as_uint(y);
    hi = __byte_perm(bx, by, 0x7632);
    const float lx = x - __uint_as_float(bx & 0xFFFF0000u);
    const float ly = y - __uint_as_float(by & 0xFFFF0000u);
    lo = __byte_perm(__float_as_uint(lx), __float_as_uint(ly), 0x7632);
}

__device__ __forceinline__ void mma_bf16(float* d, const uint32_t* a,
                                         uint32_t b0, uint32_t b1) {
    asm volatile(
        "mma.sync.aligned.m16n8k16.row.col.f32.bf16.bf16.f32 "
        "{%0,%1,%2,%3}, {%4,%5,%6,%7}, {%8,%9}, {%0,%1,%2,%3};"
        : "+f"(d[0]), "+f"(d[1]), "+f"(d[2]), "+f"(d[3])
        : "r"(a[0]), "r"(a[1]), "r"(a[2]), "r"(a[3]), "r"(b0), "r"(b1));
}

// ---------------------------------------------------------------------------
// Kernel 1: transpose x [B, C_IN, N] -> xt [B, N, C_IN]; block (0,0) also
// builds the bf16 W fragment images.
// m16n8k16 B fragment (col): b0: k=(lane%4)*2, n=lane/4; b1: k+1; b2/b3: k+8/+9.
// ---------------------------------------------------------------------------
__global__ __launch_bounds__(256) void transpose_kernel(const float* __restrict__ x,
                                                        const float* __restrict__ W,
                                                        float* __restrict__ xt,
                                                        float* __restrict__ wimg) {
    __shared__ float2 t2[32][65];          // pitch 65 (odd) float2
    const int b  = blockIdx.y;
    const int n0 = blockIdx.x * 128;
    const int tid = threadIdx.x;

#pragma unroll
    for (int k = 0; k < 4; k++) {
#pragma unroll
        for (int h = 0; h < 2; h++) {
            const int c  = (tid >> 5) + 8 * k;
            const int c2 = (tid & 31) + 32 * h;
            const int n  = n0 + 2 * c2;
            const float* xr = x + ((size_t)b * C_IN + c) * NNODE;
            float2 v = make_float2(0.f, 0.f);
            if (n + 1 < NNODE)      v = *(const float2*)(xr + n);
            else if (n < NNODE)     v.x = xr[n];
            t2[c][c2] = v;
        }
    }
    __syncthreads();

    const float* tf = (const float*)t2;    // pitch 130 floats
#pragma unroll
    for (int pass = 0; pass < 4; pass++) {
        const int nn = (tid >> 3) + 32 * pass;
        const int n  = n0 + nn;
        if (n < NNODE) {
            const int cb = 4 * (tid & 7);
            float4 o;
            o.x = tf[(cb + 0) * 130 + nn];
            o.y = tf[(cb + 1) * 130 + nn];
            o.z = tf[(cb + 2) * 130 + nn];
            o.w = tf[(cb + 3) * 130 + nn];
            *(float4*)(xt + ((size_t)b * NNODE + n) * C_IN + cb) = o;
        }
    }

    // Merged wsplit: bf16 hi/lo fragment images (uint16 slot per element).
    if (blockIdx.x == 0 && blockIdx.y == 0) {
        uint16_t* w16 = (uint16_t*)wimg;
        for (int i = tid; i < 32 * 224; i += 256) {
            const int o = i / 224, k = i % 224;
            const int j = k / 32, kk = k % 32;
            const int ks2 = kk >> 4, kloc = kk & 15;
            const int nb = o >> 3, n = o & 7;
            const int lane = n * 4 + ((kloc & 7) >> 1);
            const int pr   = kloc >> 3;        // reg pair 0/1
            const int half = kloc & 1;         // low/high bf16 in reg
            const float v = W[i];
            const uint32_t bits = __float_as_uint(v);
            const uint16_t h16 = (uint16_t)(bits >> 16);
            const float lof = v - __uint_as_float(bits & 0xFFFF0000u);
            const uint16_t l16 = (uint16_t)(__float_as_uint(lof) >> 16);
            const int wordbase = ((j * 8 + ks2 * 4 + nb) * 32 + lane) * 4;
            w16[(wordbase + pr) * 2 + half]     = h16;   // hi words 0,1
            w16[(wordbase + 2 + pr) * 2 + half] = l16;   // lo words 2,3
        }
    }
}

// ---------------------------------------------------------------------------
// Kernel 2: mma.sync bf16 conv (m16n8k16), 3-term hi/lo in registers.
// A gathered row-major (pitch 40 fl) via 16B cp.async; W via LDG.128
// (L1-resident). smem 44.5KB -> 4 CTAs/SM.
// ---------------------------------------------------------------------------
__global__ __launch_bounds__(THREADS, 4) void onering_conv_mma_kernel(
    const float* __restrict__ xt,
    const int* __restrict__ neigh,
    const float* __restrict__ wimg,
    float* __restrict__ out) {

    extern __shared__ __align__(16) char smem[];
    const uint32_t sbase = s2u(smem);
    int* sidx = (int*)(smem + SM_SIDX);

    const int tid  = threadIdx.x;
    const int wid  = tid >> 5;
    const int lane = tid & 31;
    const int b    = blockIdx.y;
    const int n0   = blockIdx.x * TM;

#pragma unroll
    for (int i = tid; i < TM * K7; i += THREADS) {
        const int gg = n0 * K7 + i;
        sidx[i] = (gg < NNODE * K7) ? neigh[gg] : 0;
    }
    __syncthreads();

    const float* xb = xt + (size_t)b * NNODE * C_IN;
    const int rsub = lane >> 3, seg = lane & 7;

    auto gather = [&](int j, int buf) {
        const uint32_t abase = sbase + SM_A + buf * (TM * PITCH * 4);
#pragma unroll
        for (int it = 0; it < 8; it++) {
            const int r = it * 16 + wid * 4 + rsub;
            const int m = sidx[r * K7 + j];
            CP_ASYNC16(abase + (uint32_t)(r * (PITCH * 4) + seg * 16),
                       xb + (size_t)m * C_IN + seg * 4);
        }
    };

    gather(0, 0);
    CP_COMMIT();

    float d[2][4][4];
#pragma unroll
    for (int mb = 0; mb < 2; mb++)
#pragma unroll
        for (int nb = 0; nb < 4; nb++)
#pragma unroll
            for (int q = 0; q < 4; q++) d[mb][nb][q] = 0.0f;

    const int g  = lane >> 2;          // fragment row within 8
    const int c2 = (lane & 3) * 2;     // fragment k base within 8
    const float4* wbase4 = (const float4*)wimg + lane;

#pragma unroll 1
    for (int j = 0; j < K7; j++) {
        const int buf = j & 1;
        if (j + 1 < K7) {
            gather(j + 1, buf ^ 1);
            CP_COMMIT();
            CP_WAIT(1);
        } else {
            CP_WAIT(0);
        }
        __syncthreads();

        const uint32_t ab = sbase + SM_A + buf * (TM * PITCH * 4);
        const float4* wj = wbase4 + (size_t)j * 256;

#pragma unroll
        for (int ks = 0; ks < 2; ks++) {
            // A fragments for both m-blocks: reg0=(r,k),reg1=(r+8,k),
            // reg2=(r,k+8),reg3=(r+8,k+8), each a bf16x2 of (k, k+1).
            uint32_t ah[2][4], al[2][4];
#pragma unroll
            for (int mb = 0; mb < 2; mb++) {
                const int r0 = wid * 32 + mb * 16 + g;
                const uint32_t a0 = ab + (uint32_t)((r0 * PITCH + ks * 16 + c2) * 4);
                float2 v0, v1, v2, v3;
                asm("ld.shared.v2.f32 {%0,%1}, [%2];" : "=f"(v0.x), "=f"(v0.y) : "r"(a0));
                asm("ld.shared.v2.f32 {%0,%1}, [%2];" : "=f"(v1.x), "=f"(v1.y) : "r"(a0 + 8 * PITCH * 4));
                asm("ld.shared.v2.f32 {%0,%1}, [%2];" : "=f"(v2.x), "=f"(v2.y) : "r"(a0 + 32));
                asm("ld.shared.v2.f32 {%0,%1}, [%2];" : "=f"(v3.x), "=f"(v3.y) : "r"(a0 + 8 * PITCH * 4 + 32));
                pack_pair(v0.x, v0.y, ah[mb][0], al[mb][0]);
                pack_pair(v1.x, v1.y, ah[mb][1], al[mb][1]);
                pack_pair(v2.x, v2.y, ah[mb][2], al[mb][2]);
                pack_pair(v3.x, v3.y, ah[mb][3], al[mb][3]);
            }
#pragma unroll
            for (int nb = 0; nb < 4; nb++) {
                const float4 wv = __ldg(wj + (ks * 4 + nb) * 32);
                const uint32_t w0 = __float_as_uint(wv.x);
                const uint32_t w1 = __float_as_uint(wv.y);
                const uint32_t w2 = __float_as_uint(wv.z);
                const uint32_t w3 = __float_as_uint(wv.w);
#pragma unroll
                for (int mb = 0; mb < 2; mb++) {
                    mma_bf16(d[mb][nb], ah[mb], w0, w1);
                    mma_bf16(d[mb][nb], al[mb], w0, w1);
                    mma_bf16(d[mb][nb], ah[mb], w2, w3);
                }
            }
        }
        __syncthreads();   // all reads of buf done before j+2 overwrites it
    }

    // Epilogue (m16n8 D layout, unchanged).
    const int r_lo = lane >> 2;
    const int c0   = 2 * (lane & 3);
#pragma unroll
    for (int mb = 0; mb < 2; mb++) {
        const int nrow = n0 + wid * 32 + mb * 16;
#pragma unroll
        for (int nb = 0; nb < 4; nb++) {
            const int o = nb * 8 + c0;
#pragma unroll
            for (int half = 0; half < 2; half++) {
                const int n = nrow + r_lo + half * 8;
                if (n < NNODE) {
                    float* ob = out + (size_t)b * C_OUT * NNODE + n;
                    ob[(size_t)o * NNODE]       = d[mb][nb][half * 2]     + cB[o];
                    ob[(size_t)(o + 1) * NNODE] = d[mb][nb][half * 2 + 1] + cB[o + 1];
                }
            }
        }
    }
}

// ---------------------------------------------------------------------------
// Launch
// ---------------------------------------------------------------------------
extern "C" void kernel_launch(void* const* d_in, const int* in_sizes, int n_in,
                              void* d_out, int out_size) {
    const float* x     = (const float*)d_in[0];
    const float* W     = (const float*)d_in[1];
    const float* bias  = (const float*)d_in[2];
    const int*   neigh = (const int*)d_in[3];
    float* out = (float*)d_out;

    float* xt = nullptr;
    cudaGetSymbolAddress((void**)&xt, g_xt);
    float* wimg = nullptr;
    cudaGetSymbolAddress((void**)&wimg, g_wimg);

    {
        dim3 grid((NNODE + 127) / 128, BATCH);
        transpose_kernel<<<grid, 256>>>(x, W, xt, wimg);
    }
    cudaMemcpyToSymbolAsync(cB, bias, C_OUT * sizeof(float), 0,
                            cudaMemcpyDeviceToDevice, 0);
    {
        cudaFuncSetAttribute(onering_conv_mma_kernel,
                             cudaFuncAttributeMaxDynamicSharedMemorySize, SM_TOTAL);
        dim3 grid(NT2, BATCH);
        onering_conv_mma_kernel<<<grid, THREADS, SM_TOTAL>>>(xt, neigh, wimg, out);
    }
}

// round 15
// speedup vs baseline: 2.1852x; 1.0372x over previous
#include <cuda_runtime.h>
#include <cstdint>

#define BATCH 4
#define C_IN 32
#define C_OUT 32
#define NNODE 163842
#define K7 7

#define TM 128                           // nodes per CTA
#define THREADS 128                      // 4 warps
#define NT2 ((NNODE + TM - 1) / TM)      // 1281
#define PITCH 40                         // A row pitch in floats (160B)

// ---- global scratch ----
__device__ float g_xt[(size_t)BATCH * NNODE * C_IN];   // x transposed [B,N,32]
// W bf16 fragment images: [j][ks2*4+nb][lane] x {hi01, hi23, lo01, lo23}
__device__ float g_wimg[K7 * 8 * 32 * 4];              // 7168 floats = 28KB
__constant__ float cB[C_OUT];

// ---- smem layout (bytes) ----
#define SM_A     0                        // 2 bufs x TM x 160 = 40960
#define SM_SIDX  40960                    // 128*7 ints = 3584
#define SM_TOTAL 44544

// ---------------------------------------------------------------------------
// helpers
// ---------------------------------------------------------------------------
__device__ __forceinline__ uint32_t s2u(const void* p) {
    uint32_t a;
    asm("{ .reg .u64 t; cvta.to.shared.u64 t, %1; cvt.u32.u64 %0, t; }"
        : "=r"(a) : "l"(p));
    return a;
}
#define CP_ASYNC16(d, s) asm volatile("cp.async.cg.shared.global [%0], [%1], 16;" :: "r"(d), "l"(s))
#define CP_COMMIT()      asm volatile("cp.async.commit_group;")
#define CP_WAIT(n)       asm volatile("cp.async.wait_group %0;" :: "n"(n))

// bf16 hi/lo pack of a value pair: hi = top-16-bit truncation (exact fp32),
// lo = (x - hi) truncated to bf16. Result regs are bf16x2 {x, y}.
__device__ __forceinline__ void pack_pair(float x, float y,
                                          uint32_t& hi, uint32_t& lo) {
    const uint32_t bx = __float_as_uint(x), by = __float_as_uint(y);
    hi = __byte_perm(bx, by, 0x7632);
    const float lx = x - __uint_as_float(bx & 0xFFFF0000u);
    const float ly = y - __uint_as_float(by & 0xFFFF0000u);
    lo = __byte_perm(__float_as_uint(lx), __float_as_uint(ly), 0x7632);
}

__device__ __forceinline__ void mma_bf16(float* d, const uint32_t* a,
                                         uint32_t b0, uint32_t b1) {
    asm volatile(
        "mma.sync.aligned.m16n8k16.row.col.f32.bf16.bf16.f32 "
        "{%0,%1,%2,%3}, {%4,%5,%6,%7}, {%8,%9}, {%0,%1,%2,%3};"
        : "+f"(d[0]), "+f"(d[1]), "+f"(d[2]), "+f"(d[3])
        : "r"(a[0]), "r"(a[1]), "r"(a[2]), "r"(a[3]), "r"(b0), "r"(b1));
}

// ---------------------------------------------------------------------------
// Kernel 1: transpose x [B, C_IN, N] -> xt [B, N, C_IN]; block (0,0) also
// builds the bf16 W fragment images.
// ---------------------------------------------------------------------------
__global__ __launch_bounds__(256) void transpose_kernel(const float* __restrict__ x,
                                                        const float* __restrict__ W,
                                                        float* __restrict__ xt,
                                                        float* __restrict__ wimg) {
    __shared__ float2 t2[32][65];          // pitch 65 (odd) float2
    const int b  = blockIdx.y;
    const int n0 = blockIdx.x * 128;
    const int tid = threadIdx.x;

#pragma unroll
    for (int k = 0; k < 4; k++) {
#pragma unroll
        for (int h = 0; h < 2; h++) {
            const int c  = (tid >> 5) + 8 * k;
            const int c2 = (tid & 31) + 32 * h;
            const int n  = n0 + 2 * c2;
            const float* xr = x + ((size_t)b * C_IN + c) * NNODE;
            float2 v = make_float2(0.f, 0.f);
            if (n + 1 < NNODE)      v = *(const float2*)(xr + n);
            else if (n < NNODE)     v.x = xr[n];
            t2[c][c2] = v;
        }
    }
    __syncthreads();

    const float* tf = (const float*)t2;    // pitch 130 floats
#pragma unroll
    for (int pass = 0; pass < 4; pass++) {
        const int nn = (tid >> 3) + 32 * pass;
        const int n  = n0 + nn;
        if (n < NNODE) {
            const int cb = 4 * (tid & 7);
            float4 o;
            o.x = tf[(cb + 0) * 130 + nn];
            o.y = tf[(cb + 1) * 130 + nn];
            o.z = tf[(cb + 2) * 130 + nn];
            o.w = tf[(cb + 3) * 130 + nn];
            *(float4*)(xt + ((size_t)b * NNODE + n) * C_IN + cb) = o;
        }
    }

    // Merged wsplit: bf16 hi/lo fragment images (uint16 slot per element).
    if (blockIdx.x == 0 && blockIdx.y == 0) {
        uint16_t* w16 = (uint16_t*)wimg;
        for (int i = tid; i < 32 * 224; i += 256) {
            const int o = i / 224, k = i % 224;
            const int j = k / 32, kk = k % 32;
            const int ks2 = kk >> 4, kloc = kk & 15;
            const int nb = o >> 3, n = o & 7;
            const int lane = n * 4 + ((kloc & 7) >> 1);
            const int pr   = kloc >> 3;        // reg pair 0/1
            const int half = kloc & 1;         // low/high bf16 in reg
            const float v = W[i];
            const uint32_t bits = __float_as_uint(v);
            const uint16_t h16 = (uint16_t)(bits >> 16);
            const float lof = v - __uint_as_float(bits & 0xFFFF0000u);
            const uint16_t l16 = (uint16_t)(__float_as_uint(lof) >> 16);
            const int wordbase = ((j * 8 + ks2 * 4 + nb) * 32 + lane) * 4;
            w16[(wordbase + pr) * 2 + half]     = h16;   // hi words 0,1
            w16[(wordbase + 2 + pr) * 2 + half] = l16;   // lo words 2,3
        }
    }
}

// ---------------------------------------------------------------------------
// Kernel 2: mma.sync bf16 conv (m16n8k16), 3-term hi/lo in registers.
// Single __syncthreads per chunk: WAIT(0) -> sync -> gather(j+1) -> compute(j).
// Safety: the sync proves all threads finished compute(j-1) (the last reader
// of buf (j+1)&1) before gather(j+1) writes it; WAIT(0) completes gather(j)
// (the only outstanding group) before compute(j) reads it.
// __launch_bounds__(128, 5): 5 CTAs/SM (smem 44.5KB x 5 = 217.5KB fits).
// ---------------------------------------------------------------------------
__global__ __launch_bounds__(THREADS, 5) void onering_conv_mma_kernel(
    const float* __restrict__ xt,
    const int* __restrict__ neigh,
    const float* __restrict__ wimg,
    float* __restrict__ out) {

    extern __shared__ __align__(16) char smem[];
    const uint32_t sbase = s2u(smem);
    int* sidx = (int*)(smem + SM_SIDX);

    const int tid  = threadIdx.x;
    const int wid  = tid >> 5;
    const int lane = tid & 31;
    const int b    = blockIdx.y;
    const int n0   = blockIdx.x * TM;

#pragma unroll
    for (int i = tid; i < TM * K7; i += THREADS) {
        const int gg = n0 * K7 + i;
        sidx[i] = (gg < NNODE * K7) ? neigh[gg] : 0;
    }
    __syncthreads();

    const float* xb = xt + (size_t)b * NNODE * C_IN;
    const int rsub = lane >> 3, seg = lane & 7;

    auto gather = [&](int j, int buf) {
        const uint32_t abase = sbase + SM_A + buf * (TM * PITCH * 4);
#pragma unroll
        for (int it = 0; it < 8; it++) {
            const int r = it * 16 + wid * 4 + rsub;
            const int m = sidx[r * K7 + j];
            CP_ASYNC16(abase + (uint32_t)(r * (PITCH * 4) + seg * 16),
                       xb + (size_t)m * C_IN + seg * 4);
        }
    };

    gather(0, 0);
    CP_COMMIT();

    float d[2][4][4];
#pragma unroll
    for (int mb = 0; mb < 2; mb++)
#pragma unroll
        for (int nb = 0; nb < 4; nb++)
#pragma unroll
            for (int q = 0; q < 4; q++) d[mb][nb][q] = 0.0f;

    const int g  = lane >> 2;          // fragment row within 8
    const int c2 = (lane & 3) * 2;     // fragment k base within 8
    const float4* wbase4 = (const float4*)wimg + lane;

#pragma unroll 1
    for (int j = 0; j < K7; j++) {
        const int buf = j & 1;
        CP_WAIT(0);                    // gather j complete
        __syncthreads();               // all threads done reading buf^1
        if (j + 1 < K7) {
            gather(j + 1, buf ^ 1);
            CP_COMMIT();
        }

        const uint32_t ab = sbase + SM_A + buf * (TM * PITCH * 4);
        const float4* wj = wbase4 + (size_t)j * 256;

#pragma unroll
        for (int ks = 0; ks < 2; ks++) {
            uint32_t ah[2][4], al[2][4];
#pragma unroll
            for (int mb = 0; mb < 2; mb++) {
                const int r0 = wid * 32 + mb * 16 + g;
                const uint32_t a0 = ab + (uint32_t)((r0 * PITCH + ks * 16 + c2) * 4);
                float2 v0, v1, v2, v3;
                asm("ld.shared.v2.f32 {%0,%1}, [%2];" : "=f"(v0.x), "=f"(v0.y) : "r"(a0));
                asm("ld.shared.v2.f32 {%0,%1}, [%2];" : "=f"(v1.x), "=f"(v1.y) : "r"(a0 + 8 * PITCH * 4));
                asm("ld.shared.v2.f32 {%0,%1}, [%2];" : "=f"(v2.x), "=f"(v2.y) : "r"(a0 + 32));
                asm("ld.shared.v2.f32 {%0,%1}, [%2];" : "=f"(v3.x), "=f"(v3.y) : "r"(a0 + 8 * PITCH * 4 + 32));
                pack_pair(v0.x, v0.y, ah[mb][0], al[mb][0]);
                pack_pair(v1.x, v1.y, ah[mb][1], al[mb][1]);
                pack_pair(v2.x, v2.y, ah[mb][2], al[mb][2]);
                pack_pair(v3.x, v3.y, ah[mb][3], al[mb][3]);
            }
#pragma unroll
            for (int nb = 0; nb < 4; nb++) {
                const float4 wv = __ldg(wj + (ks * 4 + nb) * 32);
                const uint32_t w0 = __float_as_uint(wv.x);
                const uint32_t w1 = __float_as_uint(wv.y);
                const uint32_t w2 = __float_as_uint(wv.z);
                const uint32_t w3 = __float_as_uint(wv.w);
#pragma unroll
                for (int mb = 0; mb < 2; mb++) {
                    mma_bf16(d[mb][nb], ah[mb], w0, w1);
                    mma_bf16(d[mb][nb], al[mb], w0, w1);
                    mma_bf16(d[mb][nb], ah[mb], w2, w3);
                }
            }
        }
    }

    // Epilogue (m16n8 D layout).
    const int r_lo = lane >> 2;
    const int c0   = 2 * (lane & 3);
#pragma unroll
    for (int mb = 0; mb < 2; mb++) {
        const int nrow = n0 + wid * 32 + mb * 16;
#pragma unroll
        for (int nb = 0; nb < 4; nb++) {
            const int o = nb * 8 + c0;
#pragma unroll
            for (int half = 0; half < 2; half++) {
                const int n = nrow + r_lo + half * 8;
                if (n < NNODE) {
                    float* ob = out + (size_t)b * C_OUT * NNODE + n;
                    ob[(size_t)o * NNODE]       = d[mb][nb][half * 2]     + cB[o];
                    ob[(size_t)(o + 1) * NNODE] = d[mb][nb][half * 2 + 1] + cB[o + 1];
                }
            }
        }
    }
}

// ---------------------------------------------------------------------------
// Launch
// ---------------------------------------------------------------------------
extern "C" void kernel_launch(void* const* d_in, const int* in_sizes, int n_in,
                              void* d_out, int out_size) {
    const float* x     = (const float*)d_in[0];
    const float* W     = (const float*)d_in[1];
    const float* bias  = (const float*)d_in[2];
    const int*   neigh = (const int*)d_in[3];
    float* out = (float*)d_out;

    float* xt = nullptr;
    cudaGetSymbolAddress((void**)&xt, g_xt);
    float* wimg = nullptr;
    cudaGetSymbolAddress((void**)&wimg, g_wimg);

    {
        dim3 grid((NNODE + 127) / 128, BATCH);
        transpose_kernel<<<grid, 256>>>(x, W, xt, wimg);
    }
    cudaMemcpyToSymbolAsync(cB, bias, C_OUT * sizeof(float), 0,
                            cudaMemcpyDeviceToDevice, 0);
    {
        cudaFuncSetAttribute(onering_conv_mma_kernel,
                             cudaFuncAttributeMaxDynamicSharedMemorySize, SM_TOTAL);
        dim3 grid(NT2, BATCH);
        onering_conv_mma_kernel<<<grid, THREADS, SM_TOTAL>>>(xt, neigh, wimg, out);
    }
}